// round 3
// baseline (speedup 1.0000x reference)
#include <cuda_runtime.h>
#include <cuda_bf16.h>

// CumulativeLayerNorm: B=8, K=8192, H=512, fp32.
// Single-read: per-(batch, 16-step chunk) block stages its 32KB tile in smem,
// computes per-step sum/sqsum, warp-scan over steps, then a 2-level
// deterministic lookback (super-chunk aggregates of 16 chunks) so the
// cross-chunk prefix costs a fixed ~2 warp-rounds regardless of position.

#define Hh 512
#define Kk 8192
#define TK 16
#define NC (Kk / TK)        // 512 chunks per batch
#define SUP 16              // chunks per super
#define NSUP (NC / SUP)     // 32 supers per batch
#define THREADS 256
#define NWARPS (THREADS / 32)
#define SPW (TK / NWARPS)   // 2 steps per warp
#define MAXB 16

__device__ int          g_cflag[MAXB * NC];
__device__ float        g_csum [MAXB * NC];
__device__ float        g_csq  [MAXB * NC];
__device__ int          g_sflag[MAXB * NSUP];
__device__ float        g_ssum [MAXB * NSUP];
__device__ float        g_ssq  [MAXB * NSUP];
__device__ unsigned int g_ticket;

__global__ void cln_init_kernel(int nc_flags, int ns_flags) {
    int i = blockIdx.x * blockDim.x + threadIdx.x;
    if (i == 0) g_ticket = 0u;
    for (int j = i; j < nc_flags; j += gridDim.x * blockDim.x) g_cflag[j] = 0;
    for (int j = i; j < ns_flags; j += gridDim.x * blockDim.x) g_sflag[j] = 0;
}

__global__ void __launch_bounds__(THREADS, 6)
cln_kernel(const float* __restrict__ in,
           const float* __restrict__ gamma,
           const float* __restrict__ beta,
           float* __restrict__ out)
{
    extern __shared__ float4 s_data[];           // TK * (H/4) float4 = 32 KB
    __shared__ float4 s_gb[256];                 // gamma[0:128], beta[128:256] (f4)
    __shared__ float s_sum[TK], s_sq[TK], s_mean[TK], s_istd[TK];
    __shared__ unsigned s_ticket;

    const int tid  = threadIdx.x;
    const int warp = tid >> 5;
    const int lane = tid & 31;

    if (tid == 0) s_ticket = atomicAdd(&g_ticket, 1u);

    // gamma / beta into smem (1 float4 per thread)
    if (tid < 128) s_gb[tid]       = ((const float4*)gamma)[tid];
    else           s_gb[tid]       = ((const float4*)beta)[tid - 128];

    __syncthreads();
    const unsigned ticket = s_ticket;
    const int b  = (int)(ticket / NC);
    const int c  = (int)(ticket % NC);
    const int k0 = c * TK;

    const float4* inp  = (const float4*)(in  + ((size_t)b * Kk + k0) * Hh);
    float4*       outp = (float4*)      (out + ((size_t)b * Kk + k0) * Hh);

    // ---- Phase A: load tile once, per-step sum / sqsum ----
#pragma unroll
    for (int i = 0; i < SPW; ++i) {
        const int s = warp * SPW + i;
        float sum = 0.f, sq = 0.f;
#pragma unroll
        for (int j = 0; j < 4; ++j) {
            float4 v = inp[s * (Hh / 4) + j * 32 + lane];
            s_data[s * (Hh / 4) + j * 32 + lane] = v;
            sum += v.x + v.y + v.z + v.w;
            sq  += v.x * v.x + v.y * v.y + v.z * v.z + v.w * v.w;
        }
#pragma unroll
        for (int o = 16; o > 0; o >>= 1) {
            sum += __shfl_xor_sync(0xffffffffu, sum, o);
            sq  += __shfl_xor_sync(0xffffffffu, sq,  o);
        }
        if (lane == 0) { s_sum[s] = sum; s_sq[s] = sq; }
    }
    __syncthreads();

    // ---- Phase B: warp 0 scans steps + 2-level cross-chunk prefix ----
    if (warp == 0) {
        float v1 = (lane < TK) ? s_sum[lane] : 0.f;
        float v2 = (lane < TK) ? s_sq [lane] : 0.f;
        // inclusive scan over TK steps (lanes 0..TK-1)
#pragma unroll
        for (int o = 1; o < TK; o <<= 1) {
            float t1 = __shfl_up_sync(0xffffffffu, v1, o);
            float t2 = __shfl_up_sync(0xffffffffu, v2, o);
            if (lane >= o) { v1 += t1; v2 += t2; }
        }
        const float a1 = __shfl_sync(0xffffffffu, v1, TK - 1);
        const float a2 = __shfl_sync(0xffffffffu, v2, TK - 1);

        const int cidx = b * NC + c;
        // publish this chunk's aggregate (release)
        if (lane == 0) {
            g_csum[cidx] = a1;
            g_csq [cidx] = a2;
            __threadfence();
            atomicExch(&g_cflag[cidx], 1);
        }

        const int sid = c >> 4;          // super index (0..NSUP-1)
        const int cin = c & (SUP - 1);   // chunk-within-super

        // last chunk of a super: gather the super's 16 chunk aggregates and
        // publish the super aggregate (fixed grouping -> deterministic)
        if (cin == SUP - 1) {
            float x1 = 0.f, x2 = 0.f;
            if (lane < SUP) {
                const int p = b * NC + sid * SUP + lane;
                while (*(volatile int*)&g_cflag[p] == 0) __nanosleep(32);
                __threadfence();
                x1 = *(volatile float*)&g_csum[p];
                x2 = *(volatile float*)&g_csq [p];
            }
            __syncwarp();
#pragma unroll
            for (int o = 16; o > 0; o >>= 1) {
                x1 += __shfl_xor_sync(0xffffffffu, x1, o);
                x2 += __shfl_xor_sync(0xffffffffu, x2, o);
            }
            if (lane == 0) {
                const int si = b * NSUP + sid;
                g_ssum[si] = x1;
                g_ssq [si] = x2;
                __threadfence();
                atomicExch(&g_sflag[si], 1);
            }
        }

        // consumer lookback: supers [0, sid) + chunks [sid*SUP, c) — each one
        // lane-parallel warp round; fixed grouping -> deterministic.
        float p1 = 0.f, p2 = 0.f;
        {
            float x1 = 0.f, x2 = 0.f;
            if (lane < sid) {
                const int p = b * NSUP + lane;
                while (*(volatile int*)&g_sflag[p] == 0) __nanosleep(32);
                __threadfence();
                x1 = *(volatile float*)&g_ssum[p];
                x2 = *(volatile float*)&g_ssq [p];
            }
            __syncwarp();
#pragma unroll
            for (int o = 16; o > 0; o >>= 1) {
                x1 += __shfl_xor_sync(0xffffffffu, x1, o);
                x2 += __shfl_xor_sync(0xffffffffu, x2, o);
            }
            p1 += x1; p2 += x2;
        }
        {
            float x1 = 0.f, x2 = 0.f;
            if (lane < cin) {
                const int p = b * NC + sid * SUP + lane;
                while (*(volatile int*)&g_cflag[p] == 0) __nanosleep(32);
                __threadfence();
                x1 = *(volatile float*)&g_csum[p];
                x2 = *(volatile float*)&g_csq [p];
            }
            __syncwarp();
#pragma unroll
            for (int o = 16; o > 0; o >>= 1) {
                x1 += __shfl_xor_sync(0xffffffffu, x1, o);
                x2 += __shfl_xor_sync(0xffffffffu, x2, o);
            }
            p1 += x1; p2 += x2;
        }

        if (lane < TK) {
            const float cs  = p1 + v1;
            const float cq  = p2 + v2;
            const float cnt = (float)(k0 + lane + 1) * (float)Hh;
            const float mean = cs / cnt;
            const float var  = cq / cnt - mean * mean;
            s_mean[lane] = mean;
            s_istd[lane] = rsqrtf(var + 1e-8f);
        }
    }
    __syncthreads();

    // ---- Phase C: normalize out of smem, streaming stores ----
#pragma unroll
    for (int i = 0; i < SPW; ++i) {
        const int s = warp * SPW + i;
        const float mean = s_mean[s];
        const float istd = s_istd[s];
#pragma unroll
        for (int j = 0; j < 4; ++j) {
            float4 v  = s_data[s * (Hh / 4) + j * 32 + lane];
            float4 g  = s_gb[j * 32 + lane];
            float4 bb = s_gb[128 + j * 32 + lane];
            float4 r;
            r.x = g.x * (v.x - mean) * istd + bb.x;
            r.y = g.y * (v.y - mean) * istd + bb.y;
            r.z = g.z * (v.z - mean) * istd + bb.z;
            r.w = g.w * (v.w - mean) * istd + bb.w;
            __stcs(&outp[s * (Hh / 4) + j * 32 + lane], r);
        }
    }
}

extern "C" void kernel_launch(void* const* d_in, const int* in_sizes, int n_in,
                              void* d_out, int out_size)
{
    const float* in    = (const float*)d_in[0];
    const float* gamma = (const float*)d_in[1];
    const float* beta  = (const float*)d_in[2];
    float*       out   = (float*)d_out;

    int B = in_sizes[0] / (Kk * Hh);   // 8 for this problem
    if (B > MAXB) B = MAXB;
    const int smem = TK * Hh * (int)sizeof(float);  // 32768

    cudaFuncSetAttribute(cln_kernel,
                         cudaFuncAttributeMaxDynamicSharedMemorySize, smem);

    cln_init_kernel<<<8, 256>>>(B * NC, B * NSUP);
    cln_kernel<<<B * NC, THREADS, smem>>>(in, gamma, beta, out);
}

// round 4
// speedup vs baseline: 1.1015x; 1.1015x over previous
#include <cuda_runtime.h>
#include <cuda_bf16.h>
#include <cstdint>

// CumulativeLayerNorm: B=8, K=8192, H=512, fp32.
// Persistent double-buffered single-read pipeline:
//   - 1 block/SM, 512 threads, chunk = 32 steps = 64KB tile
//   - cp.async prefetch of chunk i+1 overlaps publish/lookback/store of chunk i
//   - flat lookback: 8 warps fetch the <=8 predecessor groups in parallel

#define Hh 512
#define Kk 8192
#define TK 32
#define NC (Kk / TK)          // 256 chunks per batch
#define THREADS 512
#define NW 16
#define SPW (TK / NW)         // 2 steps per warp
#define MAXCHUNK 4096
#define TILE_BYTES (TK * Hh * 4)      // 65536
#define TILE_F4 (TK * Hh / 4)         // 4096 float4

__device__ int   g_flag[MAXCHUNK];
__device__ float g_sumv[MAXCHUNK];
__device__ float g_sqv [MAXCHUNK];

__global__ void cln_init_kernel(int n) {
    int i = blockIdx.x * blockDim.x + threadIdx.x;
    for (int j = i; j < n; j += gridDim.x * blockDim.x) g_flag[j] = 0;
}

__device__ __forceinline__ void cp_async16(uint32_t sdst, const void* gsrc) {
    asm volatile("cp.async.cg.shared.global [%0], [%1], 16;\n" :: "r"(sdst), "l"(gsrc));
}
__device__ __forceinline__ void cp_commit() {
    asm volatile("cp.async.commit_group;\n");
}
__device__ __forceinline__ void cp_wait0() {
    asm volatile("cp.async.wait_group 0;\n");
}

__global__ void __launch_bounds__(THREADS, 1)
cln_kernel(const float* __restrict__ in,
           const float* __restrict__ gamma,
           const float* __restrict__ beta,
           float* __restrict__ out,
           int B, int NTOT)
{
    extern __shared__ char smem_raw[];        // 2 * 64KB tile buffers
    __shared__ float s_gb[2 * Hh];            // gamma then beta
    __shared__ float s_sum[TK], s_sq[TK], s_mean[TK], s_istd[TK];
    __shared__ float s_p1[9], s_p2[9];

    const int tid  = threadIdx.x;
    const int warp = tid >> 5;
    const int lane = tid & 31;
    const int G    = gridDim.x;

    const uint32_t sbase = (uint32_t)__cvta_generic_to_shared(smem_raw);

    // stage gamma/beta into smem once
    if (tid < Hh / 4) {
        ((float4*)s_gb)[tid]           = ((const float4*)gamma)[tid];
        ((float4*)(s_gb + Hh))[tid]    = ((const float4*)beta)[tid];
    }

    // first prefetch
    int g0 = blockIdx.x;
    if (g0 < NTOT) {
        const int b = g0 % B, c = g0 / B;
        const float4* src = (const float4*)(in + ((size_t)b * Kk + c * TK) * Hh);
#pragma unroll
        for (int q = 0; q < TILE_F4 / THREADS; ++q) {
            const int t = tid + q * THREADS;
            cp_async16(sbase + t * 16, src + t);
        }
    }
    cp_commit();

    int it = 0;
    for (int g = g0; g < NTOT; g += G, ++it) {
        const int b  = g % B;
        const int c  = g / B;
        const int k0 = c * TK;
        float4* buf  = (float4*)(smem_raw + (size_t)(it & 1) * TILE_BYTES);

        cp_wait0();
        __syncthreads();               // tile ready; prev phase C done with other buf

        // issue prefetch of next tile ASAP (other buffer)
        const int gn = g + G;
        if (gn < NTOT) {
            const int bn = gn % B, cn = gn / B;
            const float4* src = (const float4*)(in + ((size_t)bn * Kk + cn * TK) * Hh);
            const uint32_t sdst = sbase + (uint32_t)((it + 1) & 1) * TILE_BYTES;
#pragma unroll
            for (int q = 0; q < TILE_F4 / THREADS; ++q) {
                const int t = tid + q * THREADS;
                cp_async16(sdst + t * 16, src + t);
            }
        }
        cp_commit();

        // ---- per-step sum / sqsum from smem ----
#pragma unroll
        for (int i = 0; i < SPW; ++i) {
            const int s = warp * SPW + i;
            float sum = 0.f, sq = 0.f;
#pragma unroll
            for (int j = 0; j < 4; ++j) {
                float4 v = buf[s * (Hh / 4) + j * 32 + lane];
                sum += v.x + v.y + v.z + v.w;
                sq  += v.x * v.x + v.y * v.y + v.z * v.z + v.w * v.w;
            }
#pragma unroll
            for (int o = 16; o > 0; o >>= 1) {
                sum += __shfl_xor_sync(0xffffffffu, sum, o);
                sq  += __shfl_xor_sync(0xffffffffu, sq,  o);
            }
            if (lane == 0) { s_sum[s] = sum; s_sq[s] = sq; }
        }
        __syncthreads();

        // ---- phase B: warp0 scans + publishes; warps 1..8 fetch predecessors ----
        if (warp == 0) {
            float v1 = s_sum[lane], v2 = s_sq[lane];
#pragma unroll
            for (int o = 1; o < 32; o <<= 1) {
                float t1 = __shfl_up_sync(0xffffffffu, v1, o);
                float t2 = __shfl_up_sync(0xffffffffu, v2, o);
                if (lane >= o) { v1 += t1; v2 += t2; }
            }
            const float a1 = __shfl_sync(0xffffffffu, v1, 31);
            const float a2 = __shfl_sync(0xffffffffu, v2, 31);
            if (lane == 0) {
                g_sumv[g] = a1;
                g_sqv [g] = a2;
                __threadfence();
                atomicExch(&g_flag[g], 1);
            }
            // stash own inclusive scan for after the barrier
            s_mean[lane] = v1;   // temporarily holds scan values
            s_istd[lane] = v2;
        } else if (warp <= 8) {
            const int r = warp - 1;
            const int pc = c - 1 - (r * 32 + lane);   // predecessor chunk idx
            float x1 = 0.f, x2 = 0.f;
            if (pc >= 0) {
                const int pi = pc * B + b;
                while (*(volatile int*)&g_flag[pi] == 0) __nanosleep(20);
                __threadfence();
                x1 = *(volatile float*)&g_sumv[pi];
                x2 = *(volatile float*)&g_sqv [pi];
            }
            __syncwarp();
#pragma unroll
            for (int o = 16; o > 0; o >>= 1) {
                x1 += __shfl_xor_sync(0xffffffffu, x1, o);
                x2 += __shfl_xor_sync(0xffffffffu, x2, o);
            }
            if (lane == 0) { s_p1[warp] = x1; s_p2[warp] = x2; }
        }
        __syncthreads();

        // ---- warp0: combine prefix parts, compute mean/istd per step ----
        if (warp == 0) {
            float x1 = (lane < 8) ? s_p1[lane + 1] : 0.f;
            float x2 = (lane < 8) ? s_p2[lane + 1] : 0.f;
#pragma unroll
            for (int o = 16; o > 0; o >>= 1) {
                x1 += __shfl_xor_sync(0xffffffffu, x1, o);
                x2 += __shfl_xor_sync(0xffffffffu, x2, o);
            }
            const float cs  = x1 + s_mean[lane];   // prefix + inclusive scan
            const float cq  = x2 + s_istd[lane];
            const float cnt = (float)(k0 + lane + 1) * (float)Hh;
            const float mean = cs / cnt;
            const float var  = cq / cnt - mean * mean;
            s_mean[lane] = mean;
            s_istd[lane] = rsqrtf(var + 1e-8f);
        }
        __syncthreads();

        // ---- phase C: normalize from smem, streaming stores ----
        float4* outp = (float4*)(out + ((size_t)b * Kk + k0) * Hh);
#pragma unroll
        for (int i = 0; i < SPW; ++i) {
            const int s = warp * SPW + i;
            const float mean = s_mean[s];
            const float istd = s_istd[s];
#pragma unroll
            for (int j = 0; j < 4; ++j) {
                const int idx = s * (Hh / 4) + j * 32 + lane;
                float4 v = buf[idx];
                float4 gg = ((float4*)s_gb)[j * 32 + lane];
                float4 bb = ((float4*)(s_gb + Hh))[j * 32 + lane];
                float4 r;
                r.x = gg.x * (v.x - mean) * istd + bb.x;
                r.y = gg.y * (v.y - mean) * istd + bb.y;
                r.z = gg.z * (v.z - mean) * istd + bb.z;
                r.w = gg.w * (v.w - mean) * istd + bb.w;
                __stcs(&outp[idx], r);
            }
        }
        // next iteration's cp_wait0 + __syncthreads covers buffer reuse
    }
}

extern "C" void kernel_launch(void* const* d_in, const int* in_sizes, int n_in,
                              void* d_out, int out_size)
{
    const float* in    = (const float*)d_in[0];
    const float* gamma = (const float*)d_in[1];
    const float* beta  = (const float*)d_in[2];
    float*       out   = (float*)d_out;

    int B = in_sizes[0] / (Kk * Hh);   // 8 for this problem
    const int NTOT = B * NC;

    int nsm = 148;
    cudaDeviceGetAttribute(&nsm, cudaDevAttrMultiProcessorCount, 0);

    const int smem = 2 * TILE_BYTES;   // 131072
    cudaFuncSetAttribute(cln_kernel,
                         cudaFuncAttributeMaxDynamicSharedMemorySize, smem);

    cln_init_kernel<<<8, 256>>>(NTOT);
    cln_kernel<<<nsm, THREADS, smem>>>(in, gamma, beta, out, B, NTOT);
}